// round 1
// baseline (speedup 1.0000x reference)
#include <cuda_runtime.h>
#include <cuda_bf16.h>
#include <math.h>

// MoEBase: x[2,2048,1024] -> router top-2 of 8 experts -> SwiGLU (w1,w3:[8,1024,2048], w2:[8,2048,1024])
// T=4096 tokens, D=1024, H=2048, E=8, K=2 -> exactly 8192 token-expert assignments.
//
// Pipeline (all deterministic, no atomics, graph-capturable):
//   1) router_kernel : logits -> softmax -> top2 (idx,w) per token
//   2) dispatch_kernel: per-expert compact token lists via block-wide prefix scan (8 blocks)
//   3) gemm1_kernel  : h = silu(Xe@w1_e) * (Xe@w3_e)  (dual-B tiles, gathered A)
//   4) gemm2_kernel  : y = h@w2_e, scaled by routing weight, scattered to per-(token,slot) buffer
//   5) combine_kernel: out[t] = y[t,slot0] + y[t,slot1]

#define T_TOKENS 4096
#define D_MODEL 1024
#define N_EXPERTS 8
#define HIDDEN 2048
#define CAP 4096           // per-expert capacity (worst case)

// ---------------- scratch (static device globals; no runtime allocation) ----------------
__device__ int   g_top_idx[T_TOKENS * 2];
__device__ float g_top_w[T_TOKENS * 2];
__device__ int   g_counts[N_EXPERTS];
__device__ int   g_perm[N_EXPERTS * CAP];    // token index per expert slot
__device__ float g_pw[N_EXPERTS * CAP];      // routing weight per expert slot
__device__ int   g_pslot[N_EXPERTS * CAP];   // which of the token's top-2 this expert is (0/1)
__device__ float g_hbuf[(size_t)N_EXPERTS * CAP * HIDDEN];   // 256 MB capacity layout
__device__ float g_ybuf[(size_t)T_TOKENS * 2 * D_MODEL];     // 32 MB per-(token,slot) outputs

// ---------------------------------- router ----------------------------------
__global__ void router_kernel(const float* __restrict__ x, const float* __restrict__ wr) {
    int warp = threadIdx.x >> 5;
    int lane = threadIdx.x & 31;
    int t = blockIdx.x * (blockDim.x >> 5) + warp;
    if (t >= T_TOKENS) return;

    float acc[N_EXPERTS];
#pragma unroll
    for (int e = 0; e < N_EXPERTS; e++) acc[e] = 0.f;

    const float* xr = x + (size_t)t * D_MODEL;
    for (int d = lane; d < D_MODEL; d += 32) {
        float xv = xr[d];
        const float* w = wr + d * N_EXPERTS;
#pragma unroll
        for (int e = 0; e < N_EXPERTS; e++) acc[e] += xv * w[e];
    }
#pragma unroll
    for (int off = 16; off > 0; off >>= 1) {
#pragma unroll
        for (int e = 0; e < N_EXPERTS; e++)
            acc[e] += __shfl_down_sync(0xffffffffu, acc[e], off);
    }
    if (lane == 0) {
        float m = acc[0];
#pragma unroll
        for (int e = 1; e < N_EXPERTS; e++) m = fmaxf(m, acc[e]);
        float p[N_EXPERTS], s = 0.f;
#pragma unroll
        for (int e = 0; e < N_EXPERTS; e++) { p[e] = expf(acc[e] - m); s += p[e]; }
        float inv = 1.f / s;
#pragma unroll
        for (int e = 0; e < N_EXPERTS; e++) p[e] *= inv;

        int i0 = 0; float v0 = p[0];
#pragma unroll
        for (int e = 1; e < N_EXPERTS; e++) if (p[e] > v0) { v0 = p[e]; i0 = e; }
        int i1 = -1; float v1 = -1.f;
#pragma unroll
        for (int e = 0; e < N_EXPERTS; e++) if (e != i0 && p[e] > v1) { v1 = p[e]; i1 = e; }

        g_top_idx[2 * t]     = i0;
        g_top_idx[2 * t + 1] = i1;
        g_top_w[2 * t]       = v0;
        g_top_w[2 * t + 1]   = v1;
    }
}

// ---------------------------------- dispatch ----------------------------------
// One block per expert. Deterministic compaction in token order via Hillis-Steele scan.
__global__ void dispatch_kernel() {
    int e = blockIdx.x;
    int tid = threadIdx.x;
    __shared__ int scan[256];
    __shared__ int s_base;
    if (tid == 0) s_base = 0;
    __syncthreads();

    for (int c0 = 0; c0 < T_TOKENS; c0 += 256) {
        int t = c0 + tid;
        int flag = 0, slot = 0;
        float w = 0.f;
        int i0 = g_top_idx[2 * t];
        int i1 = g_top_idx[2 * t + 1];
        if (i0 == e)      { flag = 1; slot = 0; w = g_top_w[2 * t]; }
        else if (i1 == e) { flag = 1; slot = 1; w = g_top_w[2 * t + 1]; }

        scan[tid] = flag;
        __syncthreads();
#pragma unroll
        for (int off = 1; off < 256; off <<= 1) {
            int v = scan[tid];
            if (tid >= off) v += scan[tid - off];
            __syncthreads();
            scan[tid] = v;
            __syncthreads();
        }
        int pos = s_base + scan[tid] - flag;   // exclusive position
        if (flag) {
            g_perm[e * CAP + pos]  = t;
            g_pw[e * CAP + pos]    = w;
            g_pslot[e * CAP + pos] = slot;
        }
        int total = scan[255];
        __syncthreads();
        if (tid == 0) s_base += total;
        __syncthreads();
    }
    if (tid == 0) g_counts[e] = s_base;
}

// ---------------------------------- GEMM1: h = silu(X@w1)*(X@w3) ----------------------------------
// BM=64, BN=128, BK=16, 256 threads, per-thread 4x8 per B matrix (dual-B).
__global__ __launch_bounds__(256) void gemm1_kernel(const float* __restrict__ x,
                                                    const float* __restrict__ w1,
                                                    const float* __restrict__ w3) {
    int e    = blockIdx.x >> 6;
    int mt   = blockIdx.x & 63;
    int cnt  = g_counts[e];
    int row0 = mt * 64;
    if (row0 >= cnt) return;
    int col0 = blockIdx.y * 128;

    const float* W1 = w1 + (size_t)e * D_MODEL * HIDDEN;
    const float* W3 = w3 + (size_t)e * D_MODEL * HIDDEN;

    __shared__ float As[16][64];
    __shared__ float Bs1[16][128];
    __shared__ float Bs3[16][128];
    __shared__ int s_tok[64];

    int tid = threadIdx.x;
    if (tid < 64) {
        int r = row0 + tid;
        s_tok[tid] = (r < cnt) ? g_perm[e * CAP + r] : -1;
    }
    __syncthreads();

    int tx = tid & 15;        // 0..15 -> 8 output cols each
    int ty = tid >> 4;        // 0..15 -> 4 output rows each
    int arow = tid >> 2;      // 0..63 : A row in tile
    int akq  = (tid & 3) * 4; // A k sub-offset
    int bkr  = tid >> 4;      // 0..15 : B k row
    int bcq  = (tid & 15) * 4;// 0..60 : B col quad

    int tok = s_tok[arow];
    const float* xA = x + (size_t)(tok >= 0 ? tok : 0) * D_MODEL;

    float acc1[4][8], acc3[4][8];
#pragma unroll
    for (int i = 0; i < 4; i++)
#pragma unroll
        for (int j = 0; j < 8; j++) { acc1[i][j] = 0.f; acc3[i][j] = 0.f; }

    for (int k0 = 0; k0 < D_MODEL; k0 += 16) {
        float4 av = make_float4(0.f, 0.f, 0.f, 0.f);
        if (tok >= 0) av = *(const float4*)(xA + k0 + akq);
        const float* b1p = W1 + (size_t)(k0 + bkr) * HIDDEN + col0 + bcq;
        const float* b3p = W3 + (size_t)(k0 + bkr) * HIDDEN + col0 + bcq;
        float4 b1a = *(const float4*)(b1p);
        float4 b1b = *(const float4*)(b1p + 64);
        float4 b3a = *(const float4*)(b3p);
        float4 b3b = *(const float4*)(b3p + 64);

        __syncthreads();
        As[akq + 0][arow] = av.x;
        As[akq + 1][arow] = av.y;
        As[akq + 2][arow] = av.z;
        As[akq + 3][arow] = av.w;
        *(float4*)&Bs1[bkr][bcq]      = b1a;
        *(float4*)&Bs1[bkr][bcq + 64] = b1b;
        *(float4*)&Bs3[bkr][bcq]      = b3a;
        *(float4*)&Bs3[bkr][bcq + 64] = b3b;
        __syncthreads();

#pragma unroll
        for (int kk = 0; kk < 16; kk++) {
            float4 a4 = *(const float4*)&As[kk][ty * 4];
            float4 p  = *(const float4*)&Bs1[kk][tx * 8];
            float4 q  = *(const float4*)&Bs1[kk][tx * 8 + 4];
            float4 r  = *(const float4*)&Bs3[kk][tx * 8];
            float4 s  = *(const float4*)&Bs3[kk][tx * 8 + 4];
            float av4[4] = { a4.x, a4.y, a4.z, a4.w };
            float b1v[8] = { p.x, p.y, p.z, p.w, q.x, q.y, q.z, q.w };
            float b3v[8] = { r.x, r.y, r.z, r.w, s.x, s.y, s.z, s.w };
#pragma unroll
            for (int i = 0; i < 4; i++)
#pragma unroll
                for (int j = 0; j < 8; j++) {
                    acc1[i][j] += av4[i] * b1v[j];
                    acc3[i][j] += av4[i] * b3v[j];
                }
        }
    }

    // epilogue: silu(h1) * h3
#pragma unroll
    for (int i = 0; i < 4; i++) {
        int gr = row0 + ty * 4 + i;
        if (gr < cnt) {
            float o[8];
#pragma unroll
            for (int j = 0; j < 8; j++) {
                float h1 = acc1[i][j];
                float sg = 1.f / (1.f + expf(-h1));
                o[j] = h1 * sg * acc3[i][j];
            }
            float* dst = g_hbuf + ((size_t)(e * CAP + gr)) * HIDDEN + col0 + tx * 8;
            *(float4*)(dst)     = make_float4(o[0], o[1], o[2], o[3]);
            *(float4*)(dst + 4) = make_float4(o[4], o[5], o[6], o[7]);
        }
    }
}

// ---------------------------------- GEMM2: y = (h @ w2) * route_w ----------------------------------
// BM=64, BN=128, BK=16, 256 threads, per-thread 4x8.
__global__ __launch_bounds__(256) void gemm2_kernel(const float* __restrict__ w2) {
    int e    = blockIdx.x >> 6;
    int mt   = blockIdx.x & 63;
    int cnt  = g_counts[e];
    int row0 = mt * 64;
    if (row0 >= cnt) return;
    int col0 = blockIdx.y * 128;

    const float* W2 = w2 + (size_t)e * HIDDEN * D_MODEL;

    __shared__ float As[16][64];
    __shared__ float Bs[16][128];

    int tid = threadIdx.x;
    int tx = tid & 15;
    int ty = tid >> 4;
    int arow = tid >> 2;
    int akq  = (tid & 3) * 4;
    int bkr  = tid >> 4;
    int bcq  = (tid & 15) * 4;

    bool avalid = (row0 + arow) < cnt;
    const float* hA = g_hbuf + ((size_t)(e * CAP + row0 + arow)) * HIDDEN;

    float acc[4][8];
#pragma unroll
    for (int i = 0; i < 4; i++)
#pragma unroll
        for (int j = 0; j < 8; j++) acc[i][j] = 0.f;

    for (int k0 = 0; k0 < HIDDEN; k0 += 16) {
        float4 av = make_float4(0.f, 0.f, 0.f, 0.f);
        if (avalid) av = *(const float4*)(hA + k0 + akq);
        const float* bp = W2 + (size_t)(k0 + bkr) * D_MODEL + col0 + bcq;
        float4 ba = *(const float4*)(bp);
        float4 bb = *(const float4*)(bp + 64);

        __syncthreads();
        As[akq + 0][arow] = av.x;
        As[akq + 1][arow] = av.y;
        As[akq + 2][arow] = av.z;
        As[akq + 3][arow] = av.w;
        *(float4*)&Bs[bkr][bcq]      = ba;
        *(float4*)&Bs[bkr][bcq + 64] = bb;
        __syncthreads();

#pragma unroll
        for (int kk = 0; kk < 16; kk++) {
            float4 a4 = *(const float4*)&As[kk][ty * 4];
            float4 p  = *(const float4*)&Bs[kk][tx * 8];
            float4 q  = *(const float4*)&Bs[kk][tx * 8 + 4];
            float av4[4] = { a4.x, a4.y, a4.z, a4.w };
            float bv[8]  = { p.x, p.y, p.z, p.w, q.x, q.y, q.z, q.w };
#pragma unroll
            for (int i = 0; i < 4; i++)
#pragma unroll
                for (int j = 0; j < 8; j++) acc[i][j] += av4[i] * bv[j];
        }
    }

#pragma unroll
    for (int i = 0; i < 4; i++) {
        int gr = row0 + ty * 4 + i;
        if (gr < cnt) {
            int idx   = e * CAP + gr;
            int tok   = g_perm[idx];
            int slot  = g_pslot[idx];
            float w   = g_pw[idx];
            float* dst = g_ybuf + ((size_t)(tok * 2 + slot)) * D_MODEL + col0 + tx * 8;
            *(float4*)(dst)     = make_float4(w * acc[i][0], w * acc[i][1], w * acc[i][2], w * acc[i][3]);
            *(float4*)(dst + 4) = make_float4(w * acc[i][4], w * acc[i][5], w * acc[i][6], w * acc[i][7]);
        }
    }
}

// ---------------------------------- combine ----------------------------------
__global__ void combine_kernel(float* __restrict__ out) {
    int i = blockIdx.x * blockDim.x + threadIdx.x;     // float4 index over [T, D]
    const float4* y4 = (const float4*)g_ybuf;
    float4* o4 = (float4*)out;
    int t = i >> 8;          // D/4 = 256 float4 per row
    int c = i & 255;
    float4 a = y4[(size_t)(t * 2) * 256 + c];
    float4 b = y4[(size_t)(t * 2 + 1) * 256 + c];
    o4[i] = make_float4(a.x + b.x, a.y + b.y, a.z + b.z, a.w + b.w);
}

// ---------------------------------- launch ----------------------------------
extern "C" void kernel_launch(void* const* d_in, const int* in_sizes, int n_in,
                              void* d_out, int out_size) {
    const float* x  = (const float*)d_in[0];
    const float* wr = (const float*)d_in[1];
    const float* w1 = (const float*)d_in[2];
    const float* w3 = (const float*)d_in[3];
    const float* w2 = (const float*)d_in[4];
    float* out = (float*)d_out;

    router_kernel<<<T_TOKENS / 8, 256>>>(x, wr);
    dispatch_kernel<<<N_EXPERTS, 256>>>();
    gemm1_kernel<<<dim3(N_EXPERTS * (CAP / 64), HIDDEN / 128), 256>>>(x, w1, w3);
    gemm2_kernel<<<dim3(N_EXPERTS * (CAP / 64), D_MODEL / 128), 256>>>(w2);
    combine_kernel<<<(T_TOKENS * D_MODEL / 4) / 256, 256>>>(out);
}

// round 3
// speedup vs baseline: 3.7350x; 3.7350x over previous
#include <cuda_runtime.h>
#include <cuda_bf16.h>
#include <math.h>

// MoEBase: x[2,2048,1024] -> router top-2 of 8 experts -> SwiGLU (w1,w3:[8,1024,2048], w2:[8,2048,1024])
// T=4096 tokens, D=1024, H=2048, E=8, K=2 -> 8192 token-expert assignments.
//
// Grouped GEMMs on the tensor pipe via tf32 mma.sync (m16n8k8).
//   1) router_kernel : logits -> softmax -> top2 (fp32, exact)
//   2) dispatch_kernel: deterministic per-expert compaction (no atomics)
//   3) gemm1_mma     : h = silu(Xe@w1_e) * (Xe@w3_e)   [tf32 MMA, dual-B]
//   4) gemm2_mma     : y = (h@w2_e) * route_w, scattered per (token,slot)
//   5) combine_kernel: out[t] = y[t,0] + y[t,1]

#define T_TOKENS 4096
#define D_MODEL 1024
#define N_EXPERTS 8
#define HIDDEN 2048
#define CAP 4096

// ---------------- scratch ----------------
__device__ int   g_top_idx[T_TOKENS * 2];
__device__ float g_top_w[T_TOKENS * 2];
__device__ int   g_counts[N_EXPERTS];
__device__ int   g_perm[N_EXPERTS * CAP];
__device__ float g_pw[N_EXPERTS * CAP];
__device__ int   g_pslot[N_EXPERTS * CAP];
__device__ float g_hbuf[(size_t)N_EXPERTS * CAP * HIDDEN];
__device__ float g_ybuf[(size_t)T_TOKENS * 2 * D_MODEL];

// ---------------- helpers ----------------
__device__ __forceinline__ float f2tf(float f) {
    unsigned u;
    asm("cvt.rna.tf32.f32 %0, %1;" : "=r"(u) : "f"(f));
    return __uint_as_float(u);
}

__device__ __forceinline__ void mma_tf32(float c[4],
                                         float a0, float a1, float a2, float a3,
                                         float b0, float b1) {
    unsigned A0 = __float_as_uint(a0), A1 = __float_as_uint(a1);
    unsigned A2 = __float_as_uint(a2), A3 = __float_as_uint(a3);
    unsigned B0 = __float_as_uint(b0), B1 = __float_as_uint(b1);
    asm volatile(
        "mma.sync.aligned.m16n8k8.row.col.f32.tf32.tf32.f32 "
        "{%0,%1,%2,%3}, {%4,%5,%6,%7}, {%8,%9}, {%0,%1,%2,%3};\n"
        : "+f"(c[0]), "+f"(c[1]), "+f"(c[2]), "+f"(c[3])
        : "r"(A0), "r"(A1), "r"(A2), "r"(A3), "r"(B0), "r"(B1));
}

// ---------------------------------- router ----------------------------------
__global__ void router_kernel(const float* __restrict__ x, const float* __restrict__ wr) {
    int warp = threadIdx.x >> 5;
    int lane = threadIdx.x & 31;
    int t = blockIdx.x * (blockDim.x >> 5) + warp;
    if (t >= T_TOKENS) return;

    float acc[N_EXPERTS];
#pragma unroll
    for (int e = 0; e < N_EXPERTS; e++) acc[e] = 0.f;

    const float* xr = x + (size_t)t * D_MODEL;
    for (int d = lane; d < D_MODEL; d += 32) {
        float xv = xr[d];
        const float* w = wr + d * N_EXPERTS;
#pragma unroll
        for (int e = 0; e < N_EXPERTS; e++) acc[e] += xv * w[e];
    }
#pragma unroll
    for (int off = 16; off > 0; off >>= 1) {
#pragma unroll
        for (int e = 0; e < N_EXPERTS; e++)
            acc[e] += __shfl_down_sync(0xffffffffu, acc[e], off);
    }
    if (lane == 0) {
        float m = acc[0];
#pragma unroll
        for (int e = 1; e < N_EXPERTS; e++) m = fmaxf(m, acc[e]);
        float p[N_EXPERTS], s = 0.f;
#pragma unroll
        for (int e = 0; e < N_EXPERTS; e++) { p[e] = expf(acc[e] - m); s += p[e]; }
        float inv = 1.f / s;
#pragma unroll
        for (int e = 0; e < N_EXPERTS; e++) p[e] *= inv;

        int i0 = 0; float v0 = p[0];
#pragma unroll
        for (int e = 1; e < N_EXPERTS; e++) if (p[e] > v0) { v0 = p[e]; i0 = e; }
        int i1 = -1; float v1 = -1.f;
#pragma unroll
        for (int e = 0; e < N_EXPERTS; e++) if (e != i0 && p[e] > v1) { v1 = p[e]; i1 = e; }

        g_top_idx[2 * t]     = i0;
        g_top_idx[2 * t + 1] = i1;
        g_top_w[2 * t]       = v0;
        g_top_w[2 * t + 1]   = v1;
    }
}

// ---------------------------------- dispatch ----------------------------------
__global__ void dispatch_kernel() {
    int e = blockIdx.x;
    int tid = threadIdx.x;
    __shared__ int scan[256];
    __shared__ int s_base;
    if (tid == 0) s_base = 0;
    __syncthreads();

    for (int c0 = 0; c0 < T_TOKENS; c0 += 256) {
        int t = c0 + tid;
        int flag = 0, slot = 0;
        float w = 0.f;
        int i0 = g_top_idx[2 * t];
        int i1 = g_top_idx[2 * t + 1];
        if (i0 == e)      { flag = 1; slot = 0; w = g_top_w[2 * t]; }
        else if (i1 == e) { flag = 1; slot = 1; w = g_top_w[2 * t + 1]; }

        scan[tid] = flag;
        __syncthreads();
#pragma unroll
        for (int off = 1; off < 256; off <<= 1) {
            int v = scan[tid];
            if (tid >= off) v += scan[tid - off];
            __syncthreads();
            scan[tid] = v;
            __syncthreads();
        }
        int pos = s_base + scan[tid] - flag;
        if (flag) {
            g_perm[e * CAP + pos]  = t;
            g_pw[e * CAP + pos]    = w;
            g_pslot[e * CAP + pos] = slot;
        }
        int total = scan[255];
        __syncthreads();
        if (tid == 0) s_base += total;
        __syncthreads();
    }
    if (tid == 0) g_counts[e] = s_base;
}

// ---------------------------------- GEMM1 (tf32 MMA, dual-B) ----------------------------------
// BM=128, BN=64, BK=16. 8 warps: wm in 0..3 (x32 rows), wn in 0..1 (x32 cols).
__global__ __launch_bounds__(256) void gemm1_mma(const float* __restrict__ x,
                                                 const float* __restrict__ w1,
                                                 const float* __restrict__ w3) {
    int e    = blockIdx.x >> 5;     // CAP/128 = 32 m-tiles per expert
    int mt   = blockIdx.x & 31;
    int cnt  = g_counts[e];
    int row0 = mt * 128;
    if (row0 >= cnt) return;
    int col0 = blockIdx.y * 64;

    const float* W1 = w1 + (size_t)e * D_MODEL * HIDDEN;
    const float* W3 = w3 + (size_t)e * D_MODEL * HIDDEN;

    __shared__ float As[128][20];     // padded: conflict-free frag loads
    __shared__ float Bs1[16][72];
    __shared__ float Bs3[16][72];
    __shared__ int s_tok[128];

    int tid = threadIdx.x;
    if (tid < 128) {
        int r = row0 + tid;
        s_tok[tid] = (r < cnt) ? g_perm[e * CAP + r] : -1;
    }
    __syncthreads();

    int ar  = tid >> 2;          // 0..63  (and ar+64)
    int ac4 = (tid & 3) * 4;     // 0,4,8,12
    int br  = tid >> 4;          // 0..15
    int bc4 = (tid & 15) * 4;    // 0..60

    int tokA0 = s_tok[ar];
    int tokA1 = s_tok[ar + 64];
    const float* xp0 = x + (size_t)(tokA0 >= 0 ? tokA0 : 0) * D_MODEL + ac4;
    const float* xp1 = x + (size_t)(tokA1 >= 0 ? tokA1 : 0) * D_MODEL + ac4;

    int lane = tid & 31;
    int grp  = lane >> 2;        // 0..7
    int tig  = lane & 3;         // 0..3
    int warp = tid >> 5;
    int wm   = warp >> 1;        // 0..3
    int wn   = warp & 1;         // 0..1

    float acc1[2][4][4], acc3[2][4][4];
#pragma unroll
    for (int mi = 0; mi < 2; mi++)
#pragma unroll
        for (int ni = 0; ni < 4; ni++)
#pragma unroll
            for (int q = 0; q < 4; q++) { acc1[mi][ni][q] = 0.f; acc3[mi][ni][q] = 0.f; }

    float4 av0 = make_float4(0.f, 0.f, 0.f, 0.f), av1 = av0;
    if (tokA0 >= 0) av0 = *(const float4*)(xp0);
    if (tokA1 >= 0) av1 = *(const float4*)(xp1);
    float4 b1v = *(const float4*)(W1 + (size_t)br * HIDDEN + col0 + bc4);
    float4 b3v = *(const float4*)(W3 + (size_t)br * HIDDEN + col0 + bc4);

    for (int k0 = 0; k0 < D_MODEL; k0 += 16) {
        As[ar][ac4 + 0]      = f2tf(av0.x);
        As[ar][ac4 + 1]      = f2tf(av0.y);
        As[ar][ac4 + 2]      = f2tf(av0.z);
        As[ar][ac4 + 3]      = f2tf(av0.w);
        As[ar + 64][ac4 + 0] = f2tf(av1.x);
        As[ar + 64][ac4 + 1] = f2tf(av1.y);
        As[ar + 64][ac4 + 2] = f2tf(av1.z);
        As[ar + 64][ac4 + 3] = f2tf(av1.w);
        Bs1[br][bc4 + 0] = f2tf(b1v.x);
        Bs1[br][bc4 + 1] = f2tf(b1v.y);
        Bs1[br][bc4 + 2] = f2tf(b1v.z);
        Bs1[br][bc4 + 3] = f2tf(b1v.w);
        Bs3[br][bc4 + 0] = f2tf(b3v.x);
        Bs3[br][bc4 + 1] = f2tf(b3v.y);
        Bs3[br][bc4 + 2] = f2tf(b3v.z);
        Bs3[br][bc4 + 3] = f2tf(b3v.w);
        __syncthreads();

        bool has_next = (k0 + 16) < D_MODEL;
        if (has_next) {
            int kn = k0 + 16;
            av0 = make_float4(0.f, 0.f, 0.f, 0.f); av1 = av0;
            if (tokA0 >= 0) av0 = *(const float4*)(xp0 + kn);
            if (tokA1 >= 0) av1 = *(const float4*)(xp1 + kn);
            b1v = *(const float4*)(W1 + (size_t)(kn + br) * HIDDEN + col0 + bc4);
            b3v = *(const float4*)(W3 + (size_t)(kn + br) * HIDDEN + col0 + bc4);
        }

#pragma unroll
        for (int ks = 0; ks < 16; ks += 8) {
            float af[2][4];
#pragma unroll
            for (int mi = 0; mi < 2; mi++) {
                int rb = wm * 32 + mi * 16;
                af[mi][0] = As[rb + grp][ks + tig];
                af[mi][1] = As[rb + grp + 8][ks + tig];
                af[mi][2] = As[rb + grp][ks + tig + 4];
                af[mi][3] = As[rb + grp + 8][ks + tig + 4];
            }
#pragma unroll
            for (int ni = 0; ni < 4; ni++) {
                int cb = wn * 32 + ni * 8 + grp;
                float b1f0 = Bs1[ks + tig][cb];
                float b1f1 = Bs1[ks + tig + 4][cb];
                float b3f0 = Bs3[ks + tig][cb];
                float b3f1 = Bs3[ks + tig + 4][cb];
#pragma unroll
                for (int mi = 0; mi < 2; mi++) {
                    mma_tf32(acc1[mi][ni], af[mi][0], af[mi][1], af[mi][2], af[mi][3], b1f0, b1f1);
                    mma_tf32(acc3[mi][ni], af[mi][0], af[mi][1], af[mi][2], af[mi][3], b3f0, b3f1);
                }
            }
        }
        __syncthreads();
    }

    // epilogue: silu(h1)*h3 -> g_hbuf
#pragma unroll
    for (int mi = 0; mi < 2; mi++) {
#pragma unroll
        for (int half = 0; half < 2; half++) {
            int lr = wm * 32 + mi * 16 + grp + half * 8;
            int gr = row0 + lr;
            if (gr < cnt) {
                float* dstrow = g_hbuf + ((size_t)(e * CAP + gr)) * HIDDEN + col0;
#pragma unroll
                for (int ni = 0; ni < 4; ni++) {
                    int c = wn * 32 + ni * 8 + tig * 2;
                    float h1a = acc1[mi][ni][half * 2 + 0];
                    float h1b = acc1[mi][ni][half * 2 + 1];
                    float h3a = acc3[mi][ni][half * 2 + 0];
                    float h3b = acc3[mi][ni][half * 2 + 1];
                    float oa = h1a * (1.f / (1.f + expf(-h1a))) * h3a;
                    float ob = h1b * (1.f / (1.f + expf(-h1b))) * h3b;
                    *(float2*)(dstrow + c) = make_float2(oa, ob);
                }
            }
        }
    }
}

// ---------------------------------- GEMM2 (tf32 MMA) ----------------------------------
// BM=128, BN=64, BK=16. Same warp layout. K = HIDDEN = 2048.
__global__ __launch_bounds__(256) void gemm2_mma(const float* __restrict__ w2) {
    int e    = blockIdx.x >> 5;
    int mt   = blockIdx.x & 31;
    int cnt  = g_counts[e];
    int row0 = mt * 128;
    if (row0 >= cnt) return;
    int col0 = blockIdx.y * 64;

    const float* W2 = w2 + (size_t)e * HIDDEN * D_MODEL;

    __shared__ float As[128][20];
    __shared__ float Bs[16][72];
    __shared__ int   s_tok[128];
    __shared__ int   s_slot[128];
    __shared__ float s_w[128];

    int tid = threadIdx.x;
    if (tid < 128) {
        int r = row0 + tid;
        if (r < cnt) {
            int idx = e * CAP + r;
            s_tok[tid]  = g_perm[idx];
            s_slot[tid] = g_pslot[idx];
            s_w[tid]    = g_pw[idx];
        } else {
            s_tok[tid] = -1; s_slot[tid] = 0; s_w[tid] = 0.f;
        }
    }
    __syncthreads();

    int ar  = tid >> 2;
    int ac4 = (tid & 3) * 4;
    int br  = tid >> 4;
    int bc4 = (tid & 15) * 4;

    const float* hA0 = g_hbuf + ((size_t)(e * CAP + row0 + ar)) * HIDDEN + ac4;
    const float* hA1 = g_hbuf + ((size_t)(e * CAP + row0 + ar + 64)) * HIDDEN + ac4;

    int lane = tid & 31;
    int grp  = lane >> 2;
    int tig  = lane & 3;
    int warp = tid >> 5;
    int wm   = warp >> 1;
    int wn   = warp & 1;

    float acc[2][4][4];
#pragma unroll
    for (int mi = 0; mi < 2; mi++)
#pragma unroll
        for (int ni = 0; ni < 4; ni++)
#pragma unroll
            for (int q = 0; q < 4; q++) acc[mi][ni][q] = 0.f;

    float4 av0 = *(const float4*)(hA0);
    float4 av1 = *(const float4*)(hA1);
    float4 bv  = *(const float4*)(W2 + (size_t)br * D_MODEL + col0 + bc4);

    for (int k0 = 0; k0 < HIDDEN; k0 += 16) {
        As[ar][ac4 + 0]      = f2tf(av0.x);
        As[ar][ac4 + 1]      = f2tf(av0.y);
        As[ar][ac4 + 2]      = f2tf(av0.z);
        As[ar][ac4 + 3]      = f2tf(av0.w);
        As[ar + 64][ac4 + 0] = f2tf(av1.x);
        As[ar + 64][ac4 + 1] = f2tf(av1.y);
        As[ar + 64][ac4 + 2] = f2tf(av1.z);
        As[ar + 64][ac4 + 3] = f2tf(av1.w);
        Bs[br][bc4 + 0] = f2tf(bv.x);
        Bs[br][bc4 + 1] = f2tf(bv.y);
        Bs[br][bc4 + 2] = f2tf(bv.z);
        Bs[br][bc4 + 3] = f2tf(bv.w);
        __syncthreads();

        bool has_next = (k0 + 16) < HIDDEN;
        if (has_next) {
            int kn = k0 + 16;
            av0 = *(const float4*)(hA0 + kn);
            av1 = *(const float4*)(hA1 + kn);
            bv  = *(const float4*)(W2 + (size_t)(kn + br) * D_MODEL + col0 + bc4);
        }

#pragma unroll
        for (int ks = 0; ks < 16; ks += 8) {
            float af[2][4];
#pragma unroll
            for (int mi = 0; mi < 2; mi++) {
                int rb = wm * 32 + mi * 16;
                af[mi][0] = As[rb + grp][ks + tig];
                af[mi][1] = As[rb + grp + 8][ks + tig];
                af[mi][2] = As[rb + grp][ks + tig + 4];
                af[mi][3] = As[rb + grp + 8][ks + tig + 4];
            }
#pragma unroll
            for (int ni = 0; ni < 4; ni++) {
                int cb = wn * 32 + ni * 8 + grp;
                float bf0 = Bs[ks + tig][cb];
                float bf1 = Bs[ks + tig + 4][cb];
#pragma unroll
                for (int mi = 0; mi < 2; mi++)
                    mma_tf32(acc[mi][ni], af[mi][0], af[mi][1], af[mi][2], af[mi][3], bf0, bf1);
            }
        }
        __syncthreads();
    }

    // epilogue: scale by routing weight, scatter per (token, slot)
#pragma unroll
    for (int mi = 0; mi < 2; mi++) {
#pragma unroll
        for (int half = 0; half < 2; half++) {
            int lr = wm * 32 + mi * 16 + grp + half * 8;
            int gr = row0 + lr;
            if (gr < cnt) {
                int tok   = s_tok[lr];
                int slot  = s_slot[lr];
                float w   = s_w[lr];
                float* dstrow = g_ybuf + ((size_t)(tok * 2 + slot)) * D_MODEL + col0;
#pragma unroll
                for (int ni = 0; ni < 4; ni++) {
                    int c = wn * 32 + ni * 8 + tig * 2;
                    *(float2*)(dstrow + c) = make_float2(w * acc[mi][ni][half * 2 + 0],
                                                         w * acc[mi][ni][half * 2 + 1]);
                }
            }
        }
    }
}

// ---------------------------------- combine ----------------------------------
__global__ void combine_kernel(float* __restrict__ out) {
    int i = blockIdx.x * blockDim.x + threadIdx.x;
    const float4* y4 = (const float4*)g_ybuf;
    float4* o4 = (float4*)out;
    int t = i >> 8;
    int c = i & 255;
    float4 a = y4[(size_t)(t * 2) * 256 + c];
    float4 b = y4[(size_t)(t * 2 + 1) * 256 + c];
    o4[i] = make_float4(a.x + b.x, a.y + b.y, a.z + b.z, a.w + b.w);
}

// ---------------------------------- launch ----------------------------------
extern "C" void kernel_launch(void* const* d_in, const int* in_sizes, int n_in,
                              void* d_out, int out_size) {
    const float* x  = (const float*)d_in[0];
    const float* wr = (const float*)d_in[1];
    const float* w1 = (const float*)d_in[2];
    const float* w3 = (const float*)d_in[3];
    const float* w2 = (const float*)d_in[4];
    float* out = (float*)d_out;

    router_kernel<<<T_TOKENS / 8, 256>>>(x, wr);
    dispatch_kernel<<<N_EXPERTS, 256>>>();
    gemm1_mma<<<dim3(N_EXPERTS * (CAP / 128), HIDDEN / 64), 256>>>(x, w1, w3);
    gemm2_mma<<<dim3(N_EXPERTS * (CAP / 128), D_MODEL / 64), 256>>>(w2);
    combine_kernel<<<(T_TOKENS * D_MODEL / 4) / 256, 256>>>(out);
}

// round 5
// speedup vs baseline: 4.5176x; 1.2095x over previous
#include <cuda_runtime.h>
#include <cuda_bf16.h>
#include <math.h>

// MoEBase: x[2,2048,1024] -> router top-2 of 8 experts -> SwiGLU (w1,w3:[8,1024,2048], w2:[8,2048,1024])
// Smem-traffic-optimized tf32 mma.sync.
//   gemm1: BM128 x (64+64 dual-B), BK16, double-buffered, 1 sync/iter
//   gemm2: BM128 x BN128, warp tile 32x64 (ni=8), BK16, double-buffered, 1 sync/iter

#define T_TOKENS 4096
#define D_MODEL 1024
#define N_EXPERTS 8
#define HIDDEN 2048
#define CAP 4096

// ---------------- scratch ----------------
__device__ int   g_top_idx[T_TOKENS * 2];
__device__ float g_top_w[T_TOKENS * 2];
__device__ int   g_counts[N_EXPERTS];
__device__ int   g_perm[N_EXPERTS * CAP];
__device__ float g_pw[N_EXPERTS * CAP];
__device__ int   g_pslot[N_EXPERTS * CAP];
__device__ float g_hbuf[(size_t)N_EXPERTS * CAP * HIDDEN];
__device__ float g_ybuf[(size_t)T_TOKENS * 2 * D_MODEL];

// ---------------- helpers ----------------
__device__ __forceinline__ float f2tf(float f) {
    unsigned u;
    asm("cvt.rna.tf32.f32 %0, %1;" : "=r"(u) : "f"(f));
    return __uint_as_float(u);
}

__device__ __forceinline__ void mma_tf32(float c[4],
                                         float a0, float a1, float a2, float a3,
                                         float b0, float b1) {
    unsigned A0 = __float_as_uint(a0), A1 = __float_as_uint(a1);
    unsigned A2 = __float_as_uint(a2), A3 = __float_as_uint(a3);
    unsigned B0 = __float_as_uint(b0), B1 = __float_as_uint(b1);
    asm volatile(
        "mma.sync.aligned.m16n8k8.row.col.f32.tf32.tf32.f32 "
        "{%0,%1,%2,%3}, {%4,%5,%6,%7}, {%8,%9}, {%0,%1,%2,%3};\n"
        : "+f"(c[0]), "+f"(c[1]), "+f"(c[2]), "+f"(c[3])
        : "r"(A0), "r"(A1), "r"(A2), "r"(A3), "r"(B0), "r"(B1));
}

// ---------------------------------- router ----------------------------------
__global__ void router_kernel(const float* __restrict__ x, const float* __restrict__ wr) {
    int warp = threadIdx.x >> 5;
    int lane = threadIdx.x & 31;
    int t = blockIdx.x * (blockDim.x >> 5) + warp;
    if (t >= T_TOKENS) return;

    float acc[N_EXPERTS];
#pragma unroll
    for (int e = 0; e < N_EXPERTS; e++) acc[e] = 0.f;

    const float* xr = x + (size_t)t * D_MODEL;
    for (int d = lane; d < D_MODEL; d += 32) {
        float xv = xr[d];
        const float* w = wr + d * N_EXPERTS;
#pragma unroll
        for (int e = 0; e < N_EXPERTS; e++) acc[e] += xv * w[e];
    }
#pragma unroll
    for (int off = 16; off > 0; off >>= 1) {
#pragma unroll
        for (int e = 0; e < N_EXPERTS; e++)
            acc[e] += __shfl_down_sync(0xffffffffu, acc[e], off);
    }
    if (lane == 0) {
        float m = acc[0];
#pragma unroll
        for (int e = 1; e < N_EXPERTS; e++) m = fmaxf(m, acc[e]);
        float p[N_EXPERTS], s = 0.f;
#pragma unroll
        for (int e = 0; e < N_EXPERTS; e++) { p[e] = expf(acc[e] - m); s += p[e]; }
        float inv = 1.f / s;
#pragma unroll
        for (int e = 0; e < N_EXPERTS; e++) p[e] *= inv;

        int i0 = 0; float v0 = p[0];
#pragma unroll
        for (int e = 1; e < N_EXPERTS; e++) if (p[e] > v0) { v0 = p[e]; i0 = e; }
        int i1 = -1; float v1 = -1.f;
#pragma unroll
        for (int e = 0; e < N_EXPERTS; e++) if (e != i0 && p[e] > v1) { v1 = p[e]; i1 = e; }

        g_top_idx[2 * t]     = i0;
        g_top_idx[2 * t + 1] = i1;
        g_top_w[2 * t]       = v0;
        g_top_w[2 * t + 1]   = v1;
    }
}

// ---------------------------------- dispatch ----------------------------------
__global__ void dispatch_kernel() {
    int e = blockIdx.x;
    int tid = threadIdx.x;
    __shared__ int scan[256];
    __shared__ int s_base;
    if (tid == 0) s_base = 0;
    __syncthreads();

    for (int c0 = 0; c0 < T_TOKENS; c0 += 256) {
        int t = c0 + tid;
        int flag = 0, slot = 0;
        float w = 0.f;
        int i0 = g_top_idx[2 * t];
        int i1 = g_top_idx[2 * t + 1];
        if (i0 == e)      { flag = 1; slot = 0; w = g_top_w[2 * t]; }
        else if (i1 == e) { flag = 1; slot = 1; w = g_top_w[2 * t + 1]; }

        scan[tid] = flag;
        __syncthreads();
#pragma unroll
        for (int off = 1; off < 256; off <<= 1) {
            int v = scan[tid];
            if (tid >= off) v += scan[tid - off];
            __syncthreads();
            scan[tid] = v;
            __syncthreads();
        }
        int pos = s_base + scan[tid] - flag;
        if (flag) {
            g_perm[e * CAP + pos]  = t;
            g_pw[e * CAP + pos]    = w;
            g_pslot[e * CAP + pos] = slot;
        }
        int total = scan[255];
        __syncthreads();
        if (tid == 0) s_base += total;
        __syncthreads();
    }
    if (tid == 0) g_counts[e] = s_base;
}

// ---------------------------------- GEMM1 (tf32 MMA, dual-B, double-buffered) ----------------------------------
// BM=128, BN=64 per matrix, BK=16. 8 warps: 4(m) x 2(n). Warp tile 32x(32+32).
__global__ __launch_bounds__(256, 2) void gemm1_mma(const float* __restrict__ x,
                                                    const float* __restrict__ w1,
                                                    const float* __restrict__ w3) {
    int e    = blockIdx.x >> 5;
    int mt   = blockIdx.x & 31;
    int cnt  = g_counts[e];
    int row0 = mt * 128;
    if (row0 >= cnt) return;
    int col0 = blockIdx.y * 64;

    const float* W1 = w1 + (size_t)e * D_MODEL * HIDDEN;
    const float* W3 = w3 + (size_t)e * D_MODEL * HIDDEN;

    __shared__ float As[2][128][20];
    __shared__ float Bs1[2][16][72];
    __shared__ float Bs3[2][16][72];
    __shared__ int s_tok[128];

    int tid = threadIdx.x;
    if (tid < 128) {
        int r = row0 + tid;
        s_tok[tid] = (r < cnt) ? g_perm[e * CAP + r] : -1;
    }
    __syncthreads();

    int ar  = tid >> 2;          // 0..63 (and +64)
    int ac4 = (tid & 3) * 4;
    int br  = tid >> 4;          // 0..15
    int bc4 = (tid & 15) * 4;    // 0..60

    int tokA0 = s_tok[ar];
    int tokA1 = s_tok[ar + 64];
    const float* xp0 = x + (size_t)(tokA0 >= 0 ? tokA0 : 0) * D_MODEL + ac4;
    const float* xp1 = x + (size_t)(tokA1 >= 0 ? tokA1 : 0) * D_MODEL + ac4;
    const float* b1p = W1 + (size_t)br * HIDDEN + col0 + bc4;
    const float* b3p = W3 + (size_t)br * HIDDEN + col0 + bc4;

    int lane = tid & 31;
    int grp  = lane >> 2;
    int tig  = lane & 3;
    int warp = tid >> 5;
    int wm   = warp >> 1;
    int wn   = warp & 1;

    float acc1[2][4][4], acc3[2][4][4];
#pragma unroll
    for (int mi = 0; mi < 2; mi++)
#pragma unroll
        for (int ni = 0; ni < 4; ni++)
#pragma unroll
            for (int q = 0; q < 4; q++) { acc1[mi][ni][q] = 0.f; acc3[mi][ni][q] = 0.f; }

    // prologue: prefetch k-tile 0 and store to stage 0
    float4 av0 = make_float4(0.f, 0.f, 0.f, 0.f), av1 = av0;
    if (tokA0 >= 0) av0 = *(const float4*)(xp0);
    if (tokA1 >= 0) av1 = *(const float4*)(xp1);
    float4 b1v = *(const float4*)(b1p);
    float4 b3v = *(const float4*)(b3p);

    {
        float* a0 = &As[0][ar][ac4];
        a0[0] = f2tf(av0.x); a0[1] = f2tf(av0.y); a0[2] = f2tf(av0.z); a0[3] = f2tf(av0.w);
        float* a1 = &As[0][ar + 64][ac4];
        a1[0] = f2tf(av1.x); a1[1] = f2tf(av1.y); a1[2] = f2tf(av1.z); a1[3] = f2tf(av1.w);
        float* bb1 = &Bs1[0][br][bc4];
        bb1[0] = f2tf(b1v.x); bb1[1] = f2tf(b1v.y); bb1[2] = f2tf(b1v.z); bb1[3] = f2tf(b1v.w);
        float* bb3 = &Bs3[0][br][bc4];
        bb3[0] = f2tf(b3v.x); bb3[1] = f2tf(b3v.y); bb3[2] = f2tf(b3v.z); bb3[3] = f2tf(b3v.w);
    }
    __syncthreads();

    const int NK = D_MODEL / 16;   // 64
    for (int kt = 0; kt < NK; kt++) {
        int s = kt & 1;
        bool more = (kt + 1) < NK;
        if (more) {
            int kn = (kt + 1) * 16;
            av0 = make_float4(0.f, 0.f, 0.f, 0.f); av1 = av0;
            if (tokA0 >= 0) av0 = *(const float4*)(xp0 + kn);
            if (tokA1 >= 0) av1 = *(const float4*)(xp1 + kn);
            b1v = *(const float4*)(b1p + (size_t)kn * HIDDEN);
            b3v = *(const float4*)(b3p + (size_t)kn * HIDDEN);
        }

        const float (*Asb)[20]  = As[s];
        const float (*B1b)[72]  = Bs1[s];
        const float (*B3b)[72]  = Bs3[s];
#pragma unroll
        for (int ks = 0; ks < 16; ks += 8) {
            float af[2][4];
#pragma unroll
            for (int mi = 0; mi < 2; mi++) {
                int rb = wm * 32 + mi * 16;
                af[mi][0] = Asb[rb + grp][ks + tig];
                af[mi][1] = Asb[rb + grp + 8][ks + tig];
                af[mi][2] = Asb[rb + grp][ks + tig + 4];
                af[mi][3] = Asb[rb + grp + 8][ks + tig + 4];
            }
#pragma unroll
            for (int ni = 0; ni < 4; ni++) {
                int cb = wn * 32 + ni * 8 + grp;
                float b1f0 = B1b[ks + tig][cb];
                float b1f1 = B1b[ks + tig + 4][cb];
                float b3f0 = B3b[ks + tig][cb];
                float b3f1 = B3b[ks + tig + 4][cb];
#pragma unroll
                for (int mi = 0; mi < 2; mi++) {
                    mma_tf32(acc1[mi][ni], af[mi][0], af[mi][1], af[mi][2], af[mi][3], b1f0, b1f1);
                    mma_tf32(acc3[mi][ni], af[mi][0], af[mi][1], af[mi][2], af[mi][3], b3f0, b3f1);
                }
            }
        }

        if (more) {
            int sn = s ^ 1;
            float* a0 = &As[sn][ar][ac4];
            a0[0] = f2tf(av0.x); a0[1] = f2tf(av0.y); a0[2] = f2tf(av0.z); a0[3] = f2tf(av0.w);
            float* a1 = &As[sn][ar + 64][ac4];
            a1[0] = f2tf(av1.x); a1[1] = f2tf(av1.y); a1[2] = f2tf(av1.z); a1[3] = f2tf(av1.w);
            float* bb1 = &Bs1[sn][br][bc4];
            bb1[0] = f2tf(b1v.x); bb1[1] = f2tf(b1v.y); bb1[2] = f2tf(b1v.z); bb1[3] = f2tf(b1v.w);
            float* bb3 = &Bs3[sn][br][bc4];
            bb3[0] = f2tf(b3v.x); bb3[1] = f2tf(b3v.y); bb3[2] = f2tf(b3v.z); bb3[3] = f2tf(b3v.w);
        }
        __syncthreads();
    }

    // epilogue: silu(h1)*h3 -> g_hbuf
#pragma unroll
    for (int mi = 0; mi < 2; mi++) {
#pragma unroll
        for (int half = 0; half < 2; half++) {
            int lr = wm * 32 + mi * 16 + grp + half * 8;
            int gr = row0 + lr;
            if (gr < cnt) {
                float* dstrow = g_hbuf + ((size_t)(e * CAP + gr)) * HIDDEN + col0;
#pragma unroll
                for (int ni = 0; ni < 4; ni++) {
                    int c = wn * 32 + ni * 8 + tig * 2;
                    float h1a = acc1[mi][ni][half * 2 + 0];
                    float h1b = acc1[mi][ni][half * 2 + 1];
                    float h3a = acc3[mi][ni][half * 2 + 0];
                    float h3b = acc3[mi][ni][half * 2 + 1];
                    float oa = h1a * (1.f / (1.f + expf(-h1a))) * h3a;
                    float ob = h1b * (1.f / (1.f + expf(-h1b))) * h3b;
                    *(float2*)(dstrow + c) = make_float2(oa, ob);
                }
            }
        }
    }
}

// ---------------------------------- GEMM2 (tf32 MMA, BN=128, warp 32x64, double-buffered) ----------------------------------
__global__ __launch_bounds__(256, 2) void gemm2_mma(const float* __restrict__ w2) {
    int e    = blockIdx.x >> 5;
    int mt   = blockIdx.x & 31;
    int cnt  = g_counts[e];
    int row0 = mt * 128;
    if (row0 >= cnt) return;
    int col0 = blockIdx.y * 128;

    const float* W2 = w2 + (size_t)e * HIDDEN * D_MODEL;

    __shared__ float As[2][128][20];
    __shared__ float Bs[2][16][136];
    __shared__ int   s_tok[128];
    __shared__ int   s_slot[128];
    __shared__ float s_w[128];

    int tid = threadIdx.x;
    if (tid < 128) {
        int r = row0 + tid;
        if (r < cnt) {
            int idx = e * CAP + r;
            s_tok[tid]  = g_perm[idx];
            s_slot[tid] = g_pslot[idx];
            s_w[tid]    = g_pw[idx];
        } else {
            s_tok[tid] = -1; s_slot[tid] = 0; s_w[tid] = 0.f;
        }
    }
    __syncthreads();

    int ar  = tid >> 2;          // 0..63 (and +64)
    int ac4 = (tid & 3) * 4;
    int br1 = tid >> 5;          // 0..7 (and +8)
    int bc4 = (tid & 31) * 4;    // 0..124

    const float* hA0 = g_hbuf + ((size_t)(e * CAP + row0 + ar)) * HIDDEN + ac4;
    const float* hA1 = g_hbuf + ((size_t)(e * CAP + row0 + ar + 64)) * HIDDEN + ac4;
    const float* bp0 = W2 + (size_t)br1 * D_MODEL + col0 + bc4;
    const float* bp1 = W2 + (size_t)(br1 + 8) * D_MODEL + col0 + bc4;

    int lane = tid & 31;
    int grp  = lane >> 2;
    int tig  = lane & 3;
    int warp = tid >> 5;
    int wm   = warp >> 1;       // 0..3 -> rows wm*32
    int wn   = warp & 1;        // 0..1 -> cols wn*64

    float acc[2][8][4];
#pragma unroll
    for (int mi = 0; mi < 2; mi++)
#pragma unroll
        for (int ni = 0; ni < 8; ni++)
#pragma unroll
            for (int q = 0; q < 4; q++) acc[mi][ni][q] = 0.f;

    float4 av0 = *(const float4*)(hA0);
    float4 av1 = *(const float4*)(hA1);
    float4 bv0 = *(const float4*)(bp0);
    float4 bv1 = *(const float4*)(bp1);

    {
        float* a0 = &As[0][ar][ac4];
        a0[0] = f2tf(av0.x); a0[1] = f2tf(av0.y); a0[2] = f2tf(av0.z); a0[3] = f2tf(av0.w);
        float* a1 = &As[0][ar + 64][ac4];
        a1[0] = f2tf(av1.x); a1[1] = f2tf(av1.y); a1[2] = f2tf(av1.z); a1[3] = f2tf(av1.w);
        float* b0 = &Bs[0][br1][bc4];
        b0[0] = f2tf(bv0.x); b0[1] = f2tf(bv0.y); b0[2] = f2tf(bv0.z); b0[3] = f2tf(bv0.w);
        float* b1 = &Bs[0][br1 + 8][bc4];
        b1[0] = f2tf(bv1.x); b1[1] = f2tf(bv1.y); b1[2] = f2tf(bv1.z); b1[3] = f2tf(bv1.w);
    }
    __syncthreads();

    const int NK = HIDDEN / 16;   // 128
    for (int kt = 0; kt < NK; kt++) {
        int s = kt & 1;
        bool more = (kt + 1) < NK;
        if (more) {
            int kn = (kt + 1) * 16;
            av0 = *(const float4*)(hA0 + kn);
            av1 = *(const float4*)(hA1 + kn);
            bv0 = *(const float4*)(bp0 + (size_t)kn * D_MODEL);
            bv1 = *(const float4*)(bp1 + (size_t)kn * D_MODEL);
        }

        const float (*Asb)[20]  = As[s];
        const float (*Bsb)[136] = Bs[s];
#pragma unroll
        for (int ks = 0; ks < 16; ks += 8) {
            float af[2][4];
#pragma unroll
            for (int mi = 0; mi < 2; mi++) {
                int rb = wm * 32 + mi * 16;
                af[mi][0] = Asb[rb + grp][ks + tig];
                af[mi][1] = Asb[rb + grp + 8][ks + tig];
                af[mi][2] = Asb[rb + grp][ks + tig + 4];
                af[mi][3] = Asb[rb + grp + 8][ks + tig + 4];
            }
#pragma unroll
            for (int ni = 0; ni < 8; ni++) {
                int cb = wn * 64 + ni * 8 + grp;
                float bf0 = Bsb[ks + tig][cb];
                float bf1 = Bsb[ks + tig + 4][cb];
#pragma unroll
                for (int mi = 0; mi < 2; mi++)
                    mma_tf32(acc[mi][ni], af[mi][0], af[mi][1], af[mi][2], af[mi][3], bf0, bf1);
            }
        }

        if (more) {
            int sn = s ^ 1;
            float* a0 = &As[sn][ar][ac4];
            a0[0] = f2tf(av0.x); a0[1] = f2tf(av0.y); a0[2] = f2tf(av0.z); a0[3] = f2tf(av0.w);
            float* a1 = &As[sn][ar + 64][ac4];
            a1[0] = f2tf(av1.x); a1[1] = f2tf(av1.y); a1[2] = f2tf(av1.z); a1[3] = f2tf(av1.w);
            float* b0 = &Bs[sn][br1][bc4];
            b0[0] = f2tf(bv0.x); b0[1] = f2tf(bv0.y); b0[2] = f2tf(bv0.z); b0[3] = f2tf(bv0.w);
            float* b1 = &Bs[sn][br1 + 8][bc4];
            b1[0] = f2tf(bv1.x); b1[1] = f2tf(bv1.y); b1[2] = f2tf(bv1.z); b1[3] = f2tf(bv1.w);
        }
        __syncthreads();
    }

    // epilogue: scale by routing weight, scatter per (token, slot)
#pragma unroll
    for (int mi = 0; mi < 2; mi++) {
#pragma unroll
        for (int half = 0; half < 2; half++) {
            int lr = wm * 32 + mi * 16 + grp + half * 8;
            int gr = row0 + lr;
            if (gr < cnt) {
                int tok   = s_tok[lr];
                int slot  = s_slot[lr];
                float w   = s_w[lr];
                float* dstrow = g_ybuf + ((size_t)(tok * 2 + slot)) * D_MODEL + col0;
#pragma unroll
                for (int ni = 0; ni < 8; ni++) {
                    int c = wn * 64 + ni * 8 + tig * 2;
                    *(float2*)(dstrow + c) = make_float2(w * acc[mi][ni][half * 2 + 0],
                                                         w * acc[mi][ni][half * 2 + 1]);
                }
            }
        }
    }
}

// ---------------------------------- combine ----------------------------------
__global__ void combine_kernel(float* __restrict__ out) {
    int i = blockIdx.x * blockDim.x + threadIdx.x;
    const float4* y4 = (const float4*)g_ybuf;
    float4* o4 = (float4*)out;
    int t = i >> 8;
    int c = i & 255;
    float4 a = y4[(size_t)(t * 2) * 256 + c];
    float4 b = y4[(size_t)(t * 2 + 1) * 256 + c];
    o4[i] = make_float4(a.x + b.x, a.y + b.y, a.z + b.z, a.w + b.w);
}

// ---------------------------------- launch ----------------------------------
extern "C" void kernel_launch(void* const* d_in, const int* in_sizes, int n_in,
                              void* d_out, int out_size) {
    const float* x  = (const float*)d_in[0];
    const float* wr = (const float*)d_in[1];
    const float* w1 = (const float*)d_in[2];
    const float* w3 = (const float*)d_in[3];
    const float* w2 = (const float*)d_in[4];
    float* out = (float*)d_out;

    router_kernel<<<T_TOKENS / 8, 256>>>(x, wr);
    dispatch_kernel<<<N_EXPERTS, 256>>>();
    gemm1_mma<<<dim3(N_EXPERTS * (CAP / 128), HIDDEN / 64), 256>>>(x, w1, w3);
    gemm2_mma<<<dim3(N_EXPERTS * (CAP / 128), D_MODEL / 128), 256>>>(w2);
    combine_kernel<<<(T_TOKENS * D_MODEL / 4) / 256, 256>>>(out);
}